// round 4
// baseline (speedup 1.0000x reference)
#include <cuda_runtime.h>
#include <cuda_bf16.h>
#include <math.h>
#include <stdint.h>

// Problem constants (fixed by the reference)
#define NND  50000          // nodes
#define FH   128            // F == H == 128
#define RR   8              // relations
#define EE   800000         // edges
#define NSEG (NND*RR)       // 400000 segments (dst*8 + type)
#define KC   1024           // R*H
#define KCONV (KC+FH)       // 1152
#define BN_EPS 1e-5f

// ---------------- scratch (device globals: no allocs allowed) ----------------
__device__ __align__(16) float g_h[NND*FH];          // current node features (fp32)
__device__ __align__(16) float g_c[NND*FH];          // conv output (pre-BN)
__device__ __align__(16) __nv_bfloat16 g_hhi[NND*FH]; // split h (for root term)
__device__ __align__(16) __nv_bfloat16 g_hlo[NND*FH];
__device__ __align__(16) __nv_bfloat16 g_xhi[NND*FH]; // split x (layer-1 GEMM A)
__device__ __align__(16) __nv_bfloat16 g_xlo[NND*FH];
__device__ int   g_deg[NSEG];
__device__ int   g_rowptr[NSEG+1];
__device__ int   g_cursor[NSEG];
__device__ int   g_tmp[NSEG];
__device__ int   g_bsum[512];
__device__ int   g_esrc[EE];
__device__ float g_colsum[FH];
__device__ float g_colsq[FH];
__device__ float g_coef[2*FH];
__device__ float g_w2o[FH+1];
// pre-split, pre-transposed B matrices (bf16 hi/lo, [N=128 rows][K cols] K-major)
__device__ __align__(16) __nv_bfloat16 g_Bc_hi[FH*KCONV];
__device__ __align__(16) __nv_bfloat16 g_Bc_lo[FH*KCONV];
__device__ __align__(16) __nv_bfloat16 g_B1_hi[FH*FH];
__device__ __align__(16) __nv_bfloat16 g_B1_lo[FH*FH];

// ---------------- small helpers ----------------
__device__ __forceinline__ uint32_t smem_u32(const void* p) {
    uint32_t a;
    asm("{ .reg .u64 t; cvta.to.shared.u64 t, %1; cvt.u32.u64 %0, t; }" : "=r"(a) : "l"(p));
    return a;
}
__device__ __forceinline__ void cp_async16(uint32_t dst, const void* src, int sz) {
    asm volatile("cp.async.cg.shared.global [%0], [%1], 16, %2;"
                 :: "r"(dst), "l"(src), "r"(sz) : "memory");
}
#define CP_COMMIT() asm volatile("cp.async.commit_group;" ::: "memory")
#define CP_WAIT0()  asm volatile("cp.async.wait_group 0;" ::: "memory")
__device__ __forceinline__ void mma_bf16(float* c, const uint32_t* a, const uint32_t* b) {
    asm volatile("mma.sync.aligned.m16n8k16.row.col.f32.bf16.bf16.f32 "
        "{%0,%1,%2,%3}, {%4,%5,%6,%7}, {%8,%9}, {%0,%1,%2,%3};"
        : "+f"(c[0]), "+f"(c[1]), "+f"(c[2]), "+f"(c[3])
        : "r"(a[0]), "r"(a[1]), "r"(a[2]), "r"(a[3]), "r"(b[0]), "r"(b[1]));
}
__device__ __forceinline__ void split2(float v0, float v1, uint32_t& hw, uint32_t& lw) {
    __nv_bfloat162 h, l;
    h.x = __float2bfloat16_rn(v0); h.y = __float2bfloat16_rn(v1);
    l.x = __float2bfloat16_rn(v0 - __bfloat162float(h.x));
    l.y = __float2bfloat16_rn(v1 - __bfloat162float(h.y));
    hw = *reinterpret_cast<uint32_t*>(&h);
    lw = *reinterpret_cast<uint32_t*>(&l);
}

// ---------------- CSR build ----------------
__global__ void zero_deg_k() {
    int i = blockIdx.x*blockDim.x + threadIdx.x;
    if (i < NSEG) g_deg[i] = 0;
}
__global__ void hist_k(const int* __restrict__ dst, const int* __restrict__ et) {
    int e = blockIdx.x*blockDim.x + threadIdx.x;
    if (e < EE) atomicAdd(&g_deg[dst[e]*RR + et[e]], 1);
}
__global__ void scan1_k() {
    __shared__ int s[1024];
    int t = threadIdx.x;
    int i = blockIdx.x*1024 + t;
    int v = (i < NSEG) ? g_deg[i] : 0;
    s[t] = v; __syncthreads();
    for (int off = 1; off < 1024; off <<= 1) {
        int x = (t >= off) ? s[t-off] : 0;
        __syncthreads(); s[t] += x; __syncthreads();
    }
    if (i < NSEG) g_tmp[i] = s[t];
    if (t == 1023) g_bsum[blockIdx.x] = s[t];
}
__global__ void scan2_k(int nb) {
    __shared__ int s[512];
    int t = threadIdx.x;
    s[t] = (t < nb) ? g_bsum[t] : 0; __syncthreads();
    for (int off = 1; off < 512; off <<= 1) {
        int x = (t >= off) ? s[t-off] : 0;
        __syncthreads(); s[t] += x; __syncthreads();
    }
    if (t < nb) g_bsum[t] = s[t];
}
__global__ void scan3_k() {
    int i = blockIdx.x*blockDim.x + threadIdx.x;
    if (i < NSEG) {
        int b = i >> 10;
        int incl = g_tmp[i] + (b > 0 ? g_bsum[b-1] : 0);
        g_rowptr[i+1] = incl;
        g_cursor[i]   = incl - g_deg[i];
        if (i == 0) g_rowptr[0] = 0;
    }
}
__global__ void scatter_k(const int* __restrict__ src, const int* __restrict__ dst,
                          const int* __restrict__ et) {
    int e = blockIdx.x*blockDim.x + threadIdx.x;
    if (e < EE) {
        int s = dst[e]*RR + et[e];
        int pos = atomicAdd(&g_cursor[s], 1);
        g_esrc[pos] = src[e];
    }
}

// ---------------- prep: transpose + bf16-split B matrices ----------------
__global__ void prepB_k(const float* __restrict__ W1, const float* __restrict__ weight,
                        const float* __restrict__ root) {
    int i = blockIdx.x*blockDim.x + threadIdx.x;
    const int totC = FH*KCONV;
    if (i < totC) {
        int n = i / KCONV, k = i % KCONV;
        float v = (k < KC) ? weight[(size_t)k*FH + n] : root[(size_t)(k-KC)*FH + n];
        __nv_bfloat16 h = __float2bfloat16_rn(v);
        g_Bc_hi[i] = h;
        g_Bc_lo[i] = __float2bfloat16_rn(v - __bfloat162float(h));
    } else if (i < totC + FH*FH) {
        int j = i - totC;
        int n = j / FH, k = j % FH;
        float v = W1[(size_t)k*FH + n];
        __nv_bfloat16 h = __float2bfloat16_rn(v);
        g_B1_hi[j] = h;
        g_B1_lo[j] = __float2bfloat16_rn(v - __bfloat162float(h));
    }
}
__global__ void prepX_k(const float* __restrict__ x) {
    int i = blockIdx.x*blockDim.x + threadIdx.x;
    if (i < NND*FH) {
        float v = x[i];
        __nv_bfloat16 h = __float2bfloat16_rn(v);
        g_xhi[i] = h;
        g_xlo[i] = __float2bfloat16_rn(v - __bfloat162float(h));
    }
}

// ---------------- plain split-bf16 GEMM (layer 1: x @ W1 + b1) ----------------
#define ASTRIDE 80
#define ARRB    (128*ASTRIDE)
#define STGB    (4*ARRB)
#define SMEM_GEMM (2*STGB)

__global__ void __launch_bounds__(256)
mmagemm_k(const __nv_bfloat16* __restrict__ Ah, const __nv_bfloat16* __restrict__ Al, int lda,
          int Kt,
          const __nv_bfloat16* __restrict__ Bh, const __nv_bfloat16* __restrict__ Bl, int ldb,
          const float* __restrict__ bias,
          float* __restrict__ Hf,
          __nv_bfloat16* __restrict__ Hhi, __nv_bfloat16* __restrict__ Hlo,
          int M)
{
    extern __shared__ char sm[];
    uint32_t smb = smem_u32(sm);
    int t = threadIdx.x, lane = t & 31, wid = t >> 5;
    int m0 = blockIdx.x * 128;
    int wm = (wid >> 2) * 64, wn = (wid & 3) * 32;
    int g = lane >> 2, tig = lane & 3;
    int nsteps = Kt >> 5;

    auto load_stage = [&](int s, int slot) {
        int kc = s << 5;
        #pragma unroll
        for (int i = 0; i < 8; i++) {
            int c = t + i*256;
            int arr = c >> 9, row = (c >> 2) & 127, col = c & 3;
            uint32_t dst = smb + slot*STGB + arr*ARRB + row*ASTRIDE + col*16;
            const __nv_bfloat16* src;
            int sz = 16;
            if (arr < 2) {
                int m = m0 + row;
                if (m >= M) { m = 0; sz = 0; }
                src = (arr ? Al : Ah) + (size_t)m*lda + kc + col*8;
            } else {
                src = (arr == 3 ? Bl : Bh) + (size_t)row*ldb + kc + col*8;
            }
            cp_async16(dst, src, sz);
        }
        CP_COMMIT();
    };

    float acc[4][4][4];
    #pragma unroll
    for (int a = 0; a < 4; a++)
        #pragma unroll
        for (int b = 0; b < 4; b++)
            #pragma unroll
            for (int q = 0; q < 4; q++) acc[a][b][q] = 0.f;

    load_stage(0, 0);
    if (nsteps > 1) load_stage(1, 1);

    for (int s = 0; s < nsteps; s++) {
        asm volatile("cp.async.wait_group 1;" ::: "memory");
        __syncthreads();
        const char* bs = sm + (s & 1)*STGB;
        #pragma unroll
        for (int kk = 0; kk < 2; kk++) {
            int kbyte = kk*32 + tig*4;
            uint32_t ah[4][4], al[4][4], bh[4][2], bl[4][2];
            #pragma unroll
            for (int mi = 0; mi < 4; mi++) {
                const char* p = bs + (wm + mi*16 + g)*ASTRIDE + kbyte;
                ah[mi][0] = *(const uint32_t*)(p);
                ah[mi][1] = *(const uint32_t*)(p + 8*ASTRIDE);
                ah[mi][2] = *(const uint32_t*)(p + 16);
                ah[mi][3] = *(const uint32_t*)(p + 8*ASTRIDE + 16);
                const char* q = p + ARRB;
                al[mi][0] = *(const uint32_t*)(q);
                al[mi][1] = *(const uint32_t*)(q + 8*ASTRIDE);
                al[mi][2] = *(const uint32_t*)(q + 16);
                al[mi][3] = *(const uint32_t*)(q + 8*ASTRIDE + 16);
            }
            #pragma unroll
            for (int ni = 0; ni < 4; ni++) {
                const char* p = bs + 2*ARRB + (wn + ni*8 + g)*ASTRIDE + kbyte;
                bh[ni][0] = *(const uint32_t*)(p);
                bh[ni][1] = *(const uint32_t*)(p + 16);
                const char* q = p + ARRB;
                bl[ni][0] = *(const uint32_t*)(q);
                bl[ni][1] = *(const uint32_t*)(q + 16);
            }
            #pragma unroll
            for (int mi = 0; mi < 4; mi++)
                #pragma unroll
                for (int ni = 0; ni < 4; ni++) {
                    mma_bf16(acc[mi][ni], ah[mi], bh[ni]);
                    mma_bf16(acc[mi][ni], al[mi], bh[ni]);
                    mma_bf16(acc[mi][ni], ah[mi], bl[ni]);
                }
        }
        __syncthreads();
        if (s + 2 < nsteps) load_stage(s + 2, s & 1);
        else CP_COMMIT();
    }
    CP_WAIT0();

    #pragma unroll
    for (int mi = 0; mi < 4; mi++)
        #pragma unroll
        for (int ni = 0; ni < 4; ni++) {
            int n = wn + ni*8 + tig*2;
            float b0 = bias[n], b1 = bias[n+1];
            #pragma unroll
            for (int h2 = 0; h2 < 2; h2++) {
                int m = m0 + wm + mi*16 + g + h2*8;
                if (m < M) {
                    float v0 = acc[mi][ni][2*h2]   + b0;
                    float v1 = acc[mi][ni][2*h2+1] + b1;
                    float2 f2; f2.x = v0; f2.y = v1;
                    *(float2*)(Hf + (size_t)m*FH + n) = f2;
                    uint32_t hw, lw;
                    split2(v0, v1, hw, lw);
                    *(uint32_t*)(Hhi + (size_t)m*FH + n) = hw;
                    *(uint32_t*)(Hlo + (size_t)m*FH + n) = lw;
                }
            }
        }
}

// ---------------- FUSED gather + conv GEMM + BN stats ----------------
// Per block: 128-row C tile. Loop r=0..8 (8 relations + root):
//   - cp.async prefetch B chunk (g_Bc cols r*128..) into smem
//   - r<8: gather segment-sums of g_h rows into smem A (split bf16)
//     r==8: cp.async h hi/lo tile (root term)
//   - 3-term m16n8k16 MMA over K=128
// Epilogue: +bias, write g_c, accumulate BN column stats (atomics).
#define FSTRIDE 136                 // bf16 elements per smem row
#define FROWB   (FSTRIDE*2)         // 272 bytes
#define FARR    (128*FROWB)         // 34816 bytes per array
#define SM_AH   0
#define SM_AL   FARR
#define SM_BH   (2*FARR)
#define SM_BL   (3*FARR)
#define SM_CS   (4*FARR)
#define SM_CQ   (4*FARR + 512)
#define SMEM_FUSED (4*FARR + 1024)  // 140288

__global__ void __launch_bounds__(512, 1)
fusedconv_k(const float* __restrict__ bias)
{
    extern __shared__ char sm[];
    uint32_t smb = smem_u32(sm);
    int t = threadIdx.x, lane = t & 31, wid = t >> 5;
    int m0 = blockIdx.x * 128;
    int wm = (wid >> 2) * 32, wn = (wid & 3) * 32;
    int g = lane >> 2, tig = lane & 3;

    if (t < 128) {
        *(float*)(sm + SM_CS + t*4) = 0.f;
        *(float*)(sm + SM_CQ + t*4) = 0.f;
    }

    float acc[2][4][4];
    #pragma unroll
    for (int a = 0; a < 2; a++)
        #pragma unroll
        for (int b = 0; b < 4; b++)
            #pragma unroll
            for (int q = 0; q < 4; q++) acc[a][b][q] = 0.f;

    for (int r = 0; r < 9; r++) {
        __syncthreads();   // prior MMA reads done before smem overwrite

        // issue B chunk cp.async (Bh,Bl: rows n=0..127, cols r*128..r*128+127)
        #pragma unroll
        for (int i = 0; i < 8; i++) {
            int c = t + i*512;
            int arr = c >> 11, row = (c >> 4) & 127, col = c & 15;
            uint32_t dst = smb + SM_BH + arr*FARR + row*FROWB + col*16;
            const __nv_bfloat16* src =
                (arr ? g_Bc_lo : g_Bc_hi) + (size_t)row*KCONV + r*128 + col*8;
            cp_async16(dst, src, 16);
        }

        if (r < 8) {
            CP_COMMIT();
            // gather: warp wid handles rows wid*8 .. wid*8+7
            #pragma unroll 1
            for (int rr = 0; rr < 8; rr++) {
                int row  = wid*8 + rr;
                int node = m0 + row;
                float4 a0 = make_float4(0.f,0.f,0.f,0.f);
                float4 a1 = make_float4(0.f,0.f,0.f,0.f);
                if (node < NND) {
                    int seg = node*RR + r;
                    int beg = g_rowptr[seg], end = g_rowptr[seg+1];
                    int e = beg;
                    for (; e + 1 < end; e += 2) {
                        int s0 = g_esrc[e], s1 = g_esrc[e+1];
                        float4 v0 = *((const float4*)(g_h + (size_t)s0*FH) + lane);
                        float4 v1 = *((const float4*)(g_h + (size_t)s1*FH) + lane);
                        a0.x += v0.x; a0.y += v0.y; a0.z += v0.z; a0.w += v0.w;
                        a1.x += v1.x; a1.y += v1.y; a1.z += v1.z; a1.w += v1.w;
                    }
                    if (e < end) {
                        int s0 = g_esrc[e];
                        float4 v0 = *((const float4*)(g_h + (size_t)s0*FH) + lane);
                        a0.x += v0.x; a0.y += v0.y; a0.z += v0.z; a0.w += v0.w;
                    }
                    a0.x += a1.x; a0.y += a1.y; a0.z += a1.z; a0.w += a1.w;
                }
                uint32_t h0, l0, h1, l1;
                split2(a0.x, a0.y, h0, l0);
                split2(a0.z, a0.w, h1, l1);
                uint2 hv, lv;
                hv.x = h0; hv.y = h1; lv.x = l0; lv.y = l1;
                *(uint2*)(sm + SM_AH + row*FROWB + lane*8) = hv;
                *(uint2*)(sm + SM_AL + row*FROWB + lane*8) = lv;
            }
            CP_WAIT0();
        } else {
            // root term: A tile = split h rows (aligned)
            #pragma unroll
            for (int i = 0; i < 8; i++) {
                int c = t + i*512;
                int arr = c >> 11, row = (c >> 4) & 127, col = c & 15;
                uint32_t dst = smb + SM_AH + arr*FARR + row*FROWB + col*16;
                int m = m0 + row, sz = 16;
                if (m >= NND) { m = 0; sz = 0; }
                const __nv_bfloat16* src = (arr ? g_hlo : g_hhi) + (size_t)m*FH + col*8;
                cp_async16(dst, src, sz);
            }
            CP_COMMIT();
            CP_WAIT0();
        }
        __syncthreads();

        // MMA over this K=128 chunk: 8 k16 steps, 3 terms
        #pragma unroll
        for (int kk = 0; kk < 8; kk++) {
            int kbyte = kk*32 + tig*4;
            uint32_t ah[2][4], al[2][4], bh[4][2], bl[4][2];
            #pragma unroll
            for (int mi = 0; mi < 2; mi++) {
                const char* p = sm + SM_AH + (wm + mi*16 + g)*FROWB + kbyte;
                ah[mi][0] = *(const uint32_t*)(p);
                ah[mi][1] = *(const uint32_t*)(p + 8*FROWB);
                ah[mi][2] = *(const uint32_t*)(p + 16);
                ah[mi][3] = *(const uint32_t*)(p + 8*FROWB + 16);
                const char* q = p + FARR;
                al[mi][0] = *(const uint32_t*)(q);
                al[mi][1] = *(const uint32_t*)(q + 8*FROWB);
                al[mi][2] = *(const uint32_t*)(q + 16);
                al[mi][3] = *(const uint32_t*)(q + 8*FROWB + 16);
            }
            #pragma unroll
            for (int ni = 0; ni < 4; ni++) {
                const char* p = sm + SM_BH + (wn + ni*8 + g)*FROWB + kbyte;
                bh[ni][0] = *(const uint32_t*)(p);
                bh[ni][1] = *(const uint32_t*)(p + 16);
                const char* q = p + FARR;
                bl[ni][0] = *(const uint32_t*)(q);
                bl[ni][1] = *(const uint32_t*)(q + 16);
            }
            #pragma unroll
            for (int mi = 0; mi < 2; mi++)
                #pragma unroll
                for (int ni = 0; ni < 4; ni++) {
                    mma_bf16(acc[mi][ni], ah[mi], bh[ni]);
                    mma_bf16(acc[mi][ni], al[mi], bh[ni]);
                    mma_bf16(acc[mi][ni], ah[mi], bl[ni]);
                }
        }
    }

    // epilogue: bias, store g_c, BN stats
    #pragma unroll
    for (int ni = 0; ni < 4; ni++) {
        int n = wn + ni*8 + tig*2;
        float b0 = bias[n], b1 = bias[n+1];
        float s0 = 0.f, s1 = 0.f, q0 = 0.f, q1 = 0.f;
        #pragma unroll
        for (int mi = 0; mi < 2; mi++)
            #pragma unroll
            for (int h2 = 0; h2 < 2; h2++) {
                int m = m0 + wm + mi*16 + g + h2*8;
                if (m < NND) {
                    float v0 = acc[mi][ni][2*h2]   + b0;
                    float v1 = acc[mi][ni][2*h2+1] + b1;
                    float2 f2; f2.x = v0; f2.y = v1;
                    *(float2*)(g_c + (size_t)m*FH + n) = f2;
                    s0 += v0; s1 += v1; q0 += v0*v0; q1 += v1*v1;
                }
            }
        #pragma unroll
        for (int off = 16; off >= 4; off >>= 1) {
            s0 += __shfl_down_sync(0xFFFFFFFFu, s0, off);
            s1 += __shfl_down_sync(0xFFFFFFFFu, s1, off);
            q0 += __shfl_down_sync(0xFFFFFFFFu, q0, off);
            q1 += __shfl_down_sync(0xFFFFFFFFu, q1, off);
        }
        if (lane < 4) {
            atomicAdd((float*)(sm + SM_CS) + n,     s0);
            atomicAdd((float*)(sm + SM_CS) + n + 1, s1);
            atomicAdd((float*)(sm + SM_CQ) + n,     q0);
            atomicAdd((float*)(sm + SM_CQ) + n + 1, q1);
        }
    }
    __syncthreads();
    if (t < 128) {
        atomicAdd(&g_colsum[t], *((float*)(sm + SM_CS) + t));
        atomicAdd(&g_colsq[t],  *((float*)(sm + SM_CQ) + t));
    }
}

// ---------------- BatchNorm ----------------
__global__ void zero_stats_k() {
    int c = threadIdx.x;
    if (c < FH) { g_colsum[c] = 0.f; g_colsq[c] = 0.f; }
}
__global__ void bncoef_k(const float* __restrict__ gamma, const float* __restrict__ beta) {
    int c = threadIdx.x;
    float mu  = g_colsum[c] / (float)NND;
    float var = g_colsq[c] / (float)NND - mu*mu;
    float sc  = gamma[c] * rsqrtf(var + BN_EPS);
    g_coef[c]      = sc;
    g_coef[FH + c] = beta[c] - mu * sc;
}
__global__ void bnrelu_k() {
    int i = blockIdx.x*blockDim.x + threadIdx.x;   // float4 index
    const int n4 = NND*FH/4;
    if (i < n4) {
        float4 v = *((const float4*)g_c + i);
        int cb = (i & 31) * 4;
        v.x = fmaxf(v.x * g_coef[cb+0] + g_coef[FH+cb+0], 0.f);
        v.y = fmaxf(v.y * g_coef[cb+1] + g_coef[FH+cb+1], 0.f);
        v.z = fmaxf(v.z * g_coef[cb+2] + g_coef[FH+cb+2], 0.f);
        v.w = fmaxf(v.w * g_coef[cb+3] + g_coef[FH+cb+3], 0.f);
        *((float4*)g_h + i) = v;
        uint32_t h0, l0, h1, l1;
        split2(v.x, v.y, h0, l0);
        split2(v.z, v.w, h1, l1);
        uint2 hv, lv;
        hv.x = h0; hv.y = h1; lv.x = l0; lv.y = l1;
        *reinterpret_cast<uint2*>(g_hhi + (size_t)i*4) = hv;
        *reinterpret_cast<uint2*>(g_hlo + (size_t)i*4) = lv;
    }
}

// ---------------- head ----------------
__global__ void w2o_k(const float* __restrict__ W2, const float* __restrict__ b2,
                      const float* __restrict__ Wo, const float* __restrict__ bo) {
    int c = threadIdx.x;
    float s = 0.f;
    for (int j = 0; j < FH; j++) s += W2[c*FH + j] * Wo[j];
    g_w2o[c] = s;
    if (c == 0) {
        float b = bo[0];
        for (int j = 0; j < FH; j++) b += b2[j] * Wo[j];
        g_w2o[FH] = b;
    }
}
__global__ void head_k(float* __restrict__ out) {
    int w    = (blockIdx.x*blockDim.x + threadIdx.x) >> 5;
    int lane = threadIdx.x & 31;
    if (w >= NND) return;
    float4 h  = *((const float4*)(g_h + (size_t)w*FH) + lane);
    float4 wv = *((const float4*)g_w2o + lane);
    float d = h.x*wv.x + h.y*wv.y + h.z*wv.z + h.w*wv.w;
    #pragma unroll
    for (int off = 16; off; off >>= 1) d += __shfl_down_sync(0xFFFFFFFFu, d, off);
    if (lane == 0) out[w] = 1.f / (1.f + expf(-(d + g_w2o[FH])));
}

// ---------------- launch ----------------
extern "C" void kernel_launch(void* const* d_in, const int* in_sizes, int n_in,
                              void* d_out, int out_size)
{
    const float* x      = (const float*)d_in[0];
    const int*   ei     = (const int*)  d_in[1];
    const int*   et     = (const int*)  d_in[2];
    const float* W1     = (const float*)d_in[3];
    const float* b1     = (const float*)d_in[4];
    const float* weight = (const float*)d_in[5];
    const float* root   = (const float*)d_in[6];
    const float* bias_c = (const float*)d_in[7];
    const float* gamma  = (const float*)d_in[8];
    const float* beta   = (const float*)d_in[9];
    const float* W2     = (const float*)d_in[10];
    const float* b2     = (const float*)d_in[11];
    const float* Wo     = (const float*)d_in[12];
    const float* bo     = (const float*)d_in[13];
    float* out = (float*)d_out;

    float *hP;
    __nv_bfloat16 *xHi, *xLo, *hHi, *hLo, *B1Hi, *B1Lo;
    cudaGetSymbolAddress((void**)&hP,   g_h);
    cudaGetSymbolAddress((void**)&xHi,  g_xhi);
    cudaGetSymbolAddress((void**)&xLo,  g_xlo);
    cudaGetSymbolAddress((void**)&hHi,  g_hhi);
    cudaGetSymbolAddress((void**)&hLo,  g_hlo);
    cudaGetSymbolAddress((void**)&B1Hi, g_B1_hi);
    cudaGetSymbolAddress((void**)&B1Lo, g_B1_lo);

    cudaFuncSetAttribute(mmagemm_k, cudaFuncAttributeMaxDynamicSharedMemorySize, SMEM_GEMM);
    cudaFuncSetAttribute(fusedconv_k, cudaFuncAttributeMaxDynamicSharedMemorySize, SMEM_FUSED);

    const int T = 256;
    const int nScan1 = (NSEG + 1023) / 1024;

    // ---- CSR build ----
    zero_deg_k<<<(NSEG + T-1)/T, T>>>();
    hist_k<<<(EE + T-1)/T, T>>>(ei + EE, et);
    scan1_k<<<nScan1, 1024>>>();
    scan2_k<<<1, 512>>>(nScan1);
    scan3_k<<<(NSEG + T-1)/T, T>>>();
    scatter_k<<<(EE + T-1)/T, T>>>(ei, ei + EE, et);

    // ---- prep ----
    prepB_k<<<(FH*KCONV + FH*FH + T-1)/T, T>>>(W1, weight, root);
    prepX_k<<<(NND*FH + T-1)/T, T>>>(x);

    const int gemmGrid = (NND + 127) / 128;   // 391

    // ---- layer 1: h = x @ W1 + b1 (also emits split h) ----
    mmagemm_k<<<gemmGrid, 256, SMEM_GEMM>>>(
        xHi, xLo, FH, FH, B1Hi, B1Lo, FH, b1, hP, hHi, hLo, NND);

    // ---- two fused conv + BN + ReLU layers ----
    for (int layer = 0; layer < 2; layer++) {
        zero_stats_k<<<1, FH>>>();
        fusedconv_k<<<gemmGrid, 512, SMEM_FUSED>>>(bias_c);
        bncoef_k<<<1, FH>>>(gamma, beta);
        bnrelu_k<<<(NND*FH/4 + T-1)/T, T>>>();
    }

    // ---- folded head ----
    w2o_k<<<1, FH>>>(W2, b2, Wo, bo);
    head_k<<<(NND*32 + T-1)/T, T>>>(out);
}